// round 17
// baseline (speedup 1.0000x reference)
#include <cuda_runtime.h>
#include <cuda_bf16.h>
#include <math.h>
#include <stdint.h>

// ---------------------------------------------------------------------------
// Problem constants (B=4, C=128, H=W=128, NH=8, d=16, GDFN hidden=512)
// ---------------------------------------------------------------------------
#define BATCH 4
#define CH    128
#define HW    16384
#define NHEAD 8
#define DHEAD 16
#define ALOG_SEGS 128

#if defined(__CUDA_ARCH_FEAT_SM103_ALL) || defined(__CUDA_ARCH_FEAT_SM100_ALL) || defined(__CUDA_ARCH_FAMILY_SPECIFIC__)
#define HAS_TC5 1
#else
#define HAS_TC5 0
#endif

// idesc (validated field layout from test_mma 0x8080490 / test_2cta bf16):
// dtype F32@4, atype BF16@7, btype BF16@10, N>>3 @17, M>>4 @24.  M=128, N=128.
#define IDESC_SS 0x8200490u

// ---------------------------------------------------------------------------
// Scratch (device globals)
// ---------------------------------------------------------------------------
__device__ float g_bufA[BATCH * 512 * HW];
__device__ float g_bufB[BATCH * 512 * HW];
__device__ float g_mu  [BATCH * HW];
__device__ float g_rstd[BATCH * HW];
__device__ float g_partS [32 * ALOG_SEGS * 256];
__device__ float g_partQ2[32 * ALOG_SEGS * 16];
__device__ float g_partK2[32 * ALOG_SEGS * 16];
__device__ float g_attn  [32 * 256];
// plain weights for the (never-used on sm_103a) fallback
__device__ float g_WqP [384 * 128];
__device__ float g_Wg1P[512 * 128];
__device__ float g_Wg2P[128 * 256];
__device__ float g_Weff[BATCH * 128 * 128];
// 128-row blocked-atom SW128 bf16 images, cols = [hi(K)|lo(K)] per 128-k chunk
__device__ uint8_t g_WqT  [3 * 65536];
__device__ uint8_t g_Wg1T [4 * 65536];
__device__ uint8_t g_Wg2T [131072];
__device__ uint8_t g_WeffT[BATCH * 65536];
__device__ float g_rs[896];
__device__ float g_cb[896];

// ---------------------------------------------------------------------------
// generic helpers
// ---------------------------------------------------------------------------
__device__ __forceinline__ void cp16(uint32_t dst_smem, const void* src)
{
    asm volatile("cp.async.ca.shared.global [%0], [%1], 16;" :: "r"(dst_smem), "l"(src));
}
__device__ __forceinline__ void cp_commit() { asm volatile("cp.async.commit_group;"); }
template <int N>
__device__ __forceinline__ void cp_wait() { asm volatile("cp.async.wait_group %0;" :: "n"(N)); }

__device__ __forceinline__ float gelu_exact(float v)
{
    return 0.5f * v * (1.f + erff(v * 0.70710678118654752440f));
}

// 128-row blocked-atom + SW128 byte offset (atom_offset = atom_row + atom_col*16;
// generalization of the VALIDATED 32-row layout from the passing R13 kernel).
__device__ __forceinline__ uint32_t img128(int brow, int kk)
{
    uint32_t off = (uint32_t)((((brow >> 3) + (kk >> 6) * 16)) * 1024
                 + (brow & 7) * 128 + (kk & 63) * 2);
    return off ^ ((off >> 3) & 0x70);
}

#if HAS_TC5
// ---------------------------------------------------------------------------
// tcgen05 helpers — from validated examples
// ---------------------------------------------------------------------------
__device__ __forceinline__ uint32_t elect_one_pred()
{
    uint32_t pred;
    asm volatile("{\n\t.reg .pred p;\n\telect.sync _|p, 0xFFFFFFFF;\n\t"
                 "selp.b32 %0, 1, 0, p;\n\t}" : "=r"(pred));
    return pred;
}
#define TC5_ALLOC(sptr, n)   asm volatile("tcgen05.alloc.cta_group::1.sync.aligned.shared::cta.b32 [%0], %1;" :: "r"(sptr), "r"(n) : "memory")
#define TC5_DEALLOC(t, n)    asm volatile("tcgen05.dealloc.cta_group::1.sync.aligned.b32 %0, %1;" :: "r"(t), "r"(n))
#define TC5_COMMIT(mb)       asm volatile("tcgen05.commit.cta_group::1.mbarrier::arrive::one.shared::cluster.b64 [%0];" :: "r"(mb) : "memory")
#define TC5_WAIT_LD()        asm volatile("tcgen05.wait::ld.sync.aligned;" ::: "memory")
#define TC5_FENCE_BEFORE()   asm volatile("tcgen05.fence::before_thread_sync;" ::: "memory")
#define TC5_FENCE_AFTER()    asm volatile("tcgen05.fence::after_thread_sync;" ::: "memory")
#define FENCE_ASYNC()        asm volatile("fence.proxy.async.shared::cta;" ::: "memory")
#define MBAR_INIT(mb, c)     asm volatile("mbarrier.init.shared.b64 [%0], %1;" :: "r"(mb), "r"(c) : "memory")
#define MBAR_INVAL(mb)       asm volatile("mbarrier.inval.shared.b64 [%0];" :: "r"(mb) : "memory")

#define MBAR_WAIT(mb, par) do {                                                    \
    uint32_t _mb = (mb), _p = (par), _d;                                           \
    asm volatile("{\n\t.reg .pred p;\n\t"                                          \
        "mbarrier.try_wait.parity.acquire.cta.shared::cta.b64 p, [%1], %2;\n\t"    \
        "selp.b32 %0, 1, 0, p;\n\t}" : "=r"(_d) : "r"(_mb), "r"(_p) : "memory");   \
    if (!_d) {                                                                     \
        asm volatile("{\n\t.reg .pred P1;\n\t"                                     \
            "WL_%=:\n\t"                                                           \
            "mbarrier.try_wait.parity.acquire.cta.shared::cta.b64 P1, [%0], %1, 0x989680;\n\t" \
            "@P1 bra.uni WD_%=;\n\tbra.uni WL_%=;\n\tWD_%=:\n\t}"                  \
            :: "r"(_mb), "r"(_p) : "memory");                                      \
    }                                                                              \
} while (0)

#define TC5_LD_X32(r, a)                                                           \
    asm volatile("tcgen05.ld.sync.aligned.32x32b.x32.b32 "                         \
        "{%0,%1,%2,%3,%4,%5,%6,%7,%8,%9,%10,%11,%12,%13,%14,%15,"                  \
        "%16,%17,%18,%19,%20,%21,%22,%23,%24,%25,%26,%27,%28,%29,%30,%31}, [%32];" \
        : "=r"((r)[0]),"=r"((r)[1]),"=r"((r)[2]),"=r"((r)[3]),                     \
          "=r"((r)[4]),"=r"((r)[5]),"=r"((r)[6]),"=r"((r)[7]),                     \
          "=r"((r)[8]),"=r"((r)[9]),"=r"((r)[10]),"=r"((r)[11]),                   \
          "=r"((r)[12]),"=r"((r)[13]),"=r"((r)[14]),"=r"((r)[15]),                 \
          "=r"((r)[16]),"=r"((r)[17]),"=r"((r)[18]),"=r"((r)[19]),                 \
          "=r"((r)[20]),"=r"((r)[21]),"=r"((r)[22]),"=r"((r)[23]),                 \
          "=r"((r)[24]),"=r"((r)[25]),"=r"((r)[26]),"=r"((r)[27]),                 \
          "=r"((r)[28]),"=r"((r)[29]),"=r"((r)[30]),"=r"((r)[31])                  \
        : "r"(a))

// SS-mode bf16 MMA, cta_group::1
__device__ __forceinline__ void tc5_mma_ss(uint32_t d_tmem, uint64_t a_desc,
                                           uint64_t b_desc, uint32_t acc)
{
    asm volatile(
        "{\n\t.reg .pred p;\n\tsetp.ne.u32 p, %4, 0;\n\t"
        "tcgen05.mma.cta_group::1.kind::f16 [%0], %1, %2, %3, {%5,%5,%5,%5}, p;\n\t}"
        :: "r"(d_tmem), "l"(a_desc), "l"(b_desc), "r"(IDESC_SS), "r"(acc), "r"(0u)
        : "memory");
}
// K-major SW128 descriptor (MAKE_SMEM_DESC): layout=2, version=1, SBO=64, LBO=1
__device__ __forceinline__ uint64_t mk_desc(uint32_t addr)
{
    return ((uint64_t)2 << 61) | (1ull << 46) | (64ull << 32) | (1ull << 16)
         | ((uint64_t)(addr >> 4) & 0x3FFF);
}
#endif  // HAS_TC5

// ---------------------------------------------------------------------------
// 0a) Weight prep: LN-scale, hi/lo bf16 split, 128-row tile images, rowsum/cb.
// ---------------------------------------------------------------------------
__global__ __launch_bounds__(256) void prep_w_k(const float* __restrict__ qkv_pw,
                                                const float* __restrict__ ln1w,
                                                const float* __restrict__ ln1b,
                                                const float* __restrict__ g1w,
                                                const float* __restrict__ ln2w,
                                                const float* __restrict__ ln2b,
                                                const float* __restrict__ g2w)
{
    int row  = blockIdx.x * 8 + (threadIdx.x >> 5);
    int lane = threadIdx.x & 31;

    if (row < 896) {
        const float *W, *lw, *lb;
        float* Wp;
        uint8_t* img;
        int rl;
        if (row < 384) {
            W = qkv_pw + (size_t)row * 128; lw = ln1w; lb = ln1b;
            Wp = g_WqP + (size_t)row * 128; rl = row;
            img = g_WqT + (size_t)(rl >> 7) * 65536;
        } else {
            rl = row - 384;
            W = g1w + (size_t)rl * 128; lw = ln2w; lb = ln2b;
            Wp = g_Wg1P + (size_t)rl * 128;
            img = g_Wg1T + (size_t)(rl >> 7) * 65536;
        }
        int brow = rl & 127;
        float rs = 0.f, cb = 0.f;
#pragma unroll
        for (int t = 0; t < 4; t++) {
            int c = lane + t * 32;
            float w = W[c];
            float wp = w * lw[c];
            Wp[c] = wp;
            __nv_bfloat16 hb = __float2bfloat16(wp);
            __nv_bfloat16 lbv = __float2bfloat16(wp - __bfloat162float(hb));
            *(__nv_bfloat16*)(img + img128(brow, c))       = hb;
            *(__nv_bfloat16*)(img + img128(brow, 128 + c)) = lbv;
            rs += __bfloat162float(hb) + __bfloat162float(lbv);
            cb += w * lb[c];
        }
#pragma unroll
        for (int o = 16; o > 0; o >>= 1) {
            rs += __shfl_xor_sync(0xffffffffu, rs, o);
            cb += __shfl_xor_sync(0xffffffffu, cb, o);
        }
        if (lane == 0) { g_rs[row] = rs; g_cb[row] = cb; }
    } else {
        int r = row - 896;
        int brow = r & 127;
#pragma unroll
        for (int t = 0; t < 8; t++) {
            int c = lane + t * 32;
            float w = g2w[r * 256 + c];
            g_Wg2P[r * 256 + c] = w;
            __nv_bfloat16 hb = __float2bfloat16(w);
            __nv_bfloat16 lbv = __float2bfloat16(w - __bfloat162float(hb));
            int kc = c >> 7, cl = c & 127;
            *(__nv_bfloat16*)(g_Wg2T + (size_t)kc * 65536 + img128(brow, cl))       = hb;
            *(__nv_bfloat16*)(g_Wg2T + (size_t)kc * 65536 + img128(brow, 128 + cl)) = lbv;
        }
    }
}

// ---------------------------------------------------------------------------
// 0b) Per-pixel LayerNorm stats (input x only; GDFN stats from proj MODE3)
// ---------------------------------------------------------------------------
__global__ __launch_bounds__(256) void ln_stats_k(const float* __restrict__ x,
                                                  float* __restrict__ mu,
                                                  float* __restrict__ rstd)
{
    int b  = blockIdx.y;
    int n4 = blockIdx.x * 256 + threadIdx.x;
    const float4* xb = (const float4*)(x + (size_t)b * CH * HW) + n4;
    float4 s  = make_float4(0.f, 0.f, 0.f, 0.f);
    float4 s2 = make_float4(0.f, 0.f, 0.f, 0.f);
#pragma unroll 8
    for (int c = 0; c < CH; c++) {
        float4 v = xb[(size_t)c * (HW / 4)];
        s.x += v.x; s.y += v.y; s.z += v.z; s.w += v.w;
        s2.x = fmaf(v.x, v.x, s2.x); s2.y = fmaf(v.y, v.y, s2.y);
        s2.z = fmaf(v.z, v.z, s2.z); s2.w = fmaf(v.w, v.w, s2.w);
    }
    float4 m, r;
    m.x = s.x * (1.f / CH); m.y = s.y * (1.f / CH);
    m.z = s.z * (1.f / CH); m.w = s.w * (1.f / CH);
    r.x = rsqrtf(s2.x * (1.f / CH) - m.x * m.x + 1e-5f);
    r.y = rsqrtf(s2.y * (1.f / CH) - m.y * m.y + 1e-5f);
    r.z = rsqrtf(s2.z * (1.f / CH) - m.z * m.z + 1e-5f);
    r.w = rsqrtf(s2.w * (1.f / CH) - m.w * m.w + 1e-5f);
    *(float4*)&mu  [b * HW + n4 * 4] = m;
    *(float4*)&rstd[b * HW + n4 * 4] = r;
}

// ---------------------------------------------------------------------------
// 1) tcgen05 SS bf16 GEMM, hi/lo 3-pass. D = X(px,k) * W(oc,k)^T.
//    A = X image in smem (bf16 hi/lo via STS), B = W image (cp.async verbatim).
//    TMEM = D only (128 cols). Grid (HW/128, BATCH).
//    MODE 0: plain  MODE 1: LN-in-epilogue  MODE 3: +residual +LN-stats-out
// ---------------------------------------------------------------------------
template <int MODE, bool RESID, int K, int OCT>
__global__ __launch_bounds__(256) void gemm5(
    const uint8_t* __restrict__ Bimg, size_t bimg_stride,
    const float* __restrict__ Wplain, int wp_stride,
    const float* __restrict__ X,
    float* __restrict__ mu, float* __restrict__ rstd,
    const float* __restrict__ rsum, const float* __restrict__ cbias,
    const float* __restrict__ resid,
    float* __restrict__ out, int OC, int XCH)
{
    extern __shared__ uint8_t dsm[];
    const int b = blockIdx.y, n0 = blockIdx.x * 128;
    const int tid = threadIdx.x, warp = tid >> 5, lane = tid & 31;
    const float* Xb = X + (size_t)b * XCH * HW;

    constexpr int NKC  = K / 128;           // 128-k chunks
    constexpr int AIMG = 65536;             // A images: hi 32KB + lo 32KB (per chunk set)
    constexpr int BIMG = 4 * K * 128;       // B image bytes per 128-oc tile (hi+lo)
    uint8_t* al = (uint8_t*)(((uintptr_t)dsm + 1023) & ~(uintptr_t)1023);
    const uint32_t a_s = (uint32_t)__cvta_generic_to_shared(al);        // A hi
    const uint32_t a_l = a_s + 32768;                                    // A lo
    const uint32_t b_s = a_s + AIMG;                                     // B image
    float* XSp = (float*)(al + AIMG + BIMG);                             // 16x132 stage
    const uint32_t xs = b_s + BIMG;

#if HAS_TC5
    const uint8_t* Bb = Bimg + (size_t)b * bimg_stride;
    __shared__ uint32_t s_tmem;
    __shared__ __align__(8) uint64_t s_mbar;
    const uint32_t sptr = (uint32_t)__cvta_generic_to_shared(&s_tmem);
    const uint32_t mbar = (uint32_t)__cvta_generic_to_shared(&s_mbar);

    if (warp == 0) TC5_ALLOC(sptr, 128);
    if (tid == 0) MBAR_INIT(mbar, 1);
    __syncthreads();
    uint32_t tmem;
    asm volatile("ld.shared.b32 %0, [%1];" : "=r"(tmem) : "r"(sptr));

    auto loadB = [&](int t) {
        const uint8_t* src = Bb + (size_t)t * BIMG;
        for (int i = tid; i < BIMG / 16; i += 256)
            cp16(b_s + i * 16, src + (size_t)i * 16);
        cp_commit();
    };

    // Convert X (K=128 only: this kernel uses NKC==1 for all K=128 GEMMs;
    // for K=256 the two chunks are interleaved as [hi0|lo0] then [hi1|lo1]
    // sequentially, with MMA consuming chunk kc right after its convert).
    auto convertA = [&](int kc) {
        for (int sc = 0; sc < 8; sc++) {
            for (int i = tid; i < 512; i += 256) {
                int kk = i >> 5, c4 = (i & 31) << 2;
                cp16(xs + (uint32_t)(kk * 132 + c4) * 4,
                     &Xb[(size_t)(kc * 128 + sc * 16 + kk) * HW + n0 + c4]);
            }
            cp_commit();
            cp_wait<0>();
            __syncthreads();
#pragma unroll
            for (int j = 0; j < 4; j++) {
                int p  = tid + j * 256;        // 1024 bf16x2 pairs
                int px = p & 127, kp = p >> 7; // kp 0..7
                float x0 = XSp[(kp * 2) * 132 + px];
                float x1 = XSp[(kp * 2 + 1) * 132 + px];
                __nv_bfloat16 h0 = __float2bfloat16(x0);
                __nv_bfloat16 h1 = __float2bfloat16(x1);
                __nv_bfloat162 hp; hp.x = h0; hp.y = h1;
                __nv_bfloat162 lp;
                lp.x = __float2bfloat16(x0 - __bfloat162float(h0));
                lp.y = __float2bfloat16(x1 - __bfloat162float(h1));
                uint32_t off = img128(px, sc * 16 + kp * 2);
                asm volatile("st.shared.b32 [%0], %1;" :: "r"(a_s + off), "r"(*(uint32_t*)&hp));
                asm volatile("st.shared.b32 [%0], %1;" :: "r"(a_l + off), "r"(*(uint32_t*)&lp));
            }
            __syncthreads();
        }
        FENCE_ASYNC();
        __syncthreads();
    };

    // MMA over one 128-k chunk of B image (B cols [hi(128)|lo(128)] at
    // image col base 0; pass0: Ahi*Bhi, pass1: Alo*Bhi, pass2: Ahi*Blo).
    auto mma_chunk = [&](uint32_t b_base, bool first) {
        uint64_t ad_hi = mk_desc(a_s);
        uint64_t ad_lo = mk_desc(a_l);
        uint64_t bd    = mk_desc(b_base);
#pragma unroll
        for (int pass = 0; pass < 3; pass++) {
            uint64_t ab = (pass == 1) ? ad_lo : ad_hi;
            int tbb = (pass == 2) ? 8 : 0;      // B lo half at k-steps 8..15
#pragma unroll
            for (int s = 0; s < 8; s++) {
                uint64_t ao = (uint64_t)((s >> 2) * 1024 + (s & 3) * 2);
                int tb = tbb + s;
                uint64_t bo = (uint64_t)((tb >> 2) * 1024 + (tb & 3) * 2);
                tc5_mma_ss(tmem, ab + ao, bd + bo,
                           (first && pass == 0 && s == 0) ? 0u : 1u);
            }
        }
    };

    loadB(0);
    for (int t = 0; t < OCT; t++) {
        for (int kc = 0; kc < NKC; kc++) {
            if (t == 0) {
                if (kc > 0) { MBAR_WAIT(mbar, (kc - 1) & 1); TC5_FENCE_AFTER(); }
                if (kc == 0) { cp_wait<0>(); __syncthreads(); }   // B arrived w/ converts
                convertA(kc);
            }
            if (warp == 0) {
                TC5_FENCE_AFTER();
                if (elect_one_pred()) {
                    mma_chunk(b_s + (uint32_t)kc * 65536, t == 0 && kc == 0 ? true : (kc == 0));
                    TC5_COMMIT(mbar);
                }
            }
        }
        // parity: total commits so far = t*NKC + NKC
        MBAR_WAIT(mbar, (t * NKC + NKC - 1) & 1);
        TC5_FENCE_AFTER();
        if (t + 1 < OCT) loadB(t + 1);

        // ---- epilogue: lane = px, cols = oc ----
        {
            int px  = (warp & 3) * 32 + lane;
            int cb0 = (warp >> 2) * 64;
            float mpx = 0.f, rpx = 0.f;
            if (MODE == 1) { mpx = mu[b * HW + n0 + px]; rpx = rstd[b * HW + n0 + px]; }
            float ssum = 0.f, ssq = 0.f;
#pragma unroll
            for (int h2 = 0; h2 < 2; h2++) {
                uint32_t dr[32];
                TC5_LD_X32(dr, tmem + cb0 + h2 * 32);
                TC5_WAIT_LD();
                int ocb = t * 128 + cb0 + h2 * 32;
#pragma unroll
                for (int i = 0; i < 32; i++) {
                    int oc = ocb + i;
                    float v = __uint_as_float(dr[i]);
                    if (MODE == 1) v = rpx * (v - mpx * rsum[oc]) + cbias[oc];
                    size_t o = ((size_t)b * OC + oc) * HW + n0 + px;
                    if (RESID) v += resid[o];
                    if (MODE == 3) { ssum += v; ssq = fmaf(v, v, ssq); }
                    out[o] = v;
                }
            }
            TC5_FENCE_BEFORE();
            if (MODE == 3) {
                float* SS  = XSp;             // [2][128]
                float* SS2 = XSp + 256;       // [2][128]
                SS [(warp >> 2) * 128 + px] = ssum;
                SS2[(warp >> 2) * 128 + px] = ssq;
                __syncthreads();
                if (tid < 128) {
                    float s = SS[tid] + SS[128 + tid];
                    float q = SS2[tid] + SS2[128 + tid];
                    float m = s * (1.f / 128.f);
                    float var = q * (1.f / 128.f) - m * m;
                    mu  [b * HW + n0 + tid] = m;
                    rstd[b * HW + n0 + tid] = rsqrtf(var + 1e-5f);
                }
            }
        }
        if (t + 1 < OCT) {
            cp_wait<0>();
            __syncthreads();
            FENCE_ASYNC();
        }
    }

    if (tid == 0) MBAR_INVAL(mbar);
    __syncthreads();
    if (warp == 0) TC5_DEALLOC(tmem, 128);

#else
    // ---- fallback: naive (correct; never used on sm_103a) ----
    (void)Bimg; (void)bimg_stride;
    const float* Wb = Wplain + (size_t)b * wp_stride;
    for (int t = 0; t < OCT; t++) {
        for (int i = tid; i < 128 * 128; i += 256) {
            int ocl = i >> 7, px = i & 127;
            int oc = t * 128 + ocl;
            float s = 0.f;
            for (int k = 0; k < K; k++)
                s = fmaf(Wb[(size_t)oc * K + k], Xb[(size_t)k * HW + n0 + px], s);
            if (MODE == 1)
                s = rstd[b * HW + n0 + px] * (s - mu[b * HW + n0 + px] * rsum[oc]) + cbias[oc];
            size_t o = ((size_t)b * OC + oc) * HW + n0 + px;
            if (RESID) s += resid[o];
            out[o] = s;
        }
    }
    if (MODE == 3) {
        __syncthreads();
        if (tid < 128) {
            float s = 0.f, q = 0.f;
            for (int oc = 0; oc < 128; oc++) {
                float v = out[((size_t)b * OC + oc) * HW + n0 + tid];
                s += v; q = fmaf(v, v, q);
            }
            float m = s * (1.f / 128.f);
            mu  [b * HW + n0 + tid] = m;
            rstd[b * HW + n0 + tid] = rsqrtf(q * (1.f / 128.f) - m * m + 1e-5f);
        }
    }
#endif
}

// ---------------------------------------------------------------------------
// 2) Depthwise 3x3 conv, 128x32 tiles
// ---------------------------------------------------------------------------
__global__ __launch_bounds__(256) void dwconv_k(const float* __restrict__ in,
                                                const float* __restrict__ wd,
                                                float* __restrict__ out,
                                                int CHN)
{
    __shared__ float t[34][136];
    int plane = blockIdx.y;
    int ch    = plane % CHN;
    size_t base = (size_t)plane * HW;
    int y0  = blockIdx.x * 32;
    int tid = threadIdx.x;

    if (tid < 68) t[tid >> 1][3 + (tid & 1) * 129] = 0.f;
#pragma unroll
    for (int i = tid; i < 1088; i += 256) {
        int r = i >> 5, c4 = (i & 31) << 2;
        int gy = y0 - 1 + r;
        float4 v = make_float4(0.f, 0.f, 0.f, 0.f);
        if (gy >= 0 && gy < 128) v = *(const float4*)&in[base + gy * 128 + c4];
        *(float4*)&t[r][4 + c4] = v;
    }
    __syncthreads();

    float w[9];
#pragma unroll
    for (int j = 0; j < 9; j++) w[j] = wd[ch * 9 + j];

    int x4 = (tid & 31) << 2;
    int r0 = tid >> 5;
#pragma unroll
    for (int rr = 0; rr < 32; rr += 8) {
        int row = r0 + rr;
        float4 o = make_float4(0.f, 0.f, 0.f, 0.f);
#pragma unroll
        for (int dy = 0; dy < 3; dy++) {
            const float* tr = &t[row + dy][4 + x4];
            float m0 = tr[-1], m1 = tr[0], m2 = tr[1], m3 = tr[2], m4 = tr[3], m5 = tr[4];
            float a = w[dy * 3 + 0], bw = w[dy * 3 + 1], c = w[dy * 3 + 2];
            o.x = fmaf(a, m0, fmaf(bw, m1, fmaf(c, m2, o.x)));
            o.y = fmaf(a, m1, fmaf(bw, m2, fmaf(c, m3, o.y)));
            o.z = fmaf(a, m2, fmaf(bw, m3, fmaf(c, m4, o.z)));
            o.w = fmaf(a, m3, fmaf(bw, m4, fmaf(c, m5, o.w)));
        }
        *(float4*)&out[base + (y0 + row) * 128 + x4] = o;
    }
}

// ---------------------------------------------------------------------------
// 2b) GDFN dwconv + gelu gate, 128x32 tiles
// ---------------------------------------------------------------------------
__global__ __launch_bounds__(256) void dwgate_k(const float* __restrict__ in,
                                                const float* __restrict__ wd,
                                                float* __restrict__ out)
{
    __shared__ float t1[34][136];
    __shared__ float t2[34][136];
    int plane = blockIdx.y;
    int b  = plane >> 8, ch = plane & 255;
    size_t base1 = ((size_t)b * 512 + ch) * HW;
    size_t base2 = ((size_t)b * 512 + 256 + ch) * HW;
    size_t baseo = ((size_t)b * 256 + ch) * HW;
    int y0  = blockIdx.x * 32;
    int tid = threadIdx.x;

    if (tid < 68) {
        t1[tid >> 1][3 + (tid & 1) * 129] = 0.f;
        t2[tid >> 1][3 + (tid & 1) * 129] = 0.f;
    }
#pragma unroll
    for (int i = tid; i < 1088; i += 256) {
        int r = i >> 5, c4 = (i & 31) << 2;
        int gy = y0 - 1 + r;
        float4 v1 = make_float4(0.f, 0.f, 0.f, 0.f);
        float4 v2 = make_float4(0.f, 0.f, 0.f, 0.f);
        if (gy >= 0 && gy < 128) {
            v1 = *(const float4*)&in[base1 + gy * 128 + c4];
            v2 = *(const float4*)&in[base2 + gy * 128 + c4];
        }
        *(float4*)&t1[r][4 + c4] = v1;
        *(float4*)&t2[r][4 + c4] = v2;
    }
    __syncthreads();

    float wA[9], wB[9];
#pragma unroll
    for (int j = 0; j < 9; j++) { wA[j] = wd[ch * 9 + j]; wB[j] = wd[(256 + ch) * 9 + j]; }

    int x4 = (tid & 31) << 2;
    int r0 = tid >> 5;
#pragma unroll
    for (int rr = 0; rr < 32; rr += 8) {
        int row = r0 + rr;
        float4 o1 = make_float4(0.f, 0.f, 0.f, 0.f);
        float4 o2 = make_float4(0.f, 0.f, 0.f, 0.f);
#pragma unroll
        for (int dy = 0; dy < 3; dy++) {
            {
                const float* tr = &t1[row + dy][4 + x4];
                float m0 = tr[-1], m1 = tr[0], m2 = tr[1], m3 = tr[2], m4 = tr[3], m5 = tr[4];
                float a = wA[dy * 3 + 0], bw = wA[dy * 3 + 1], c = wA[dy * 3 + 2];
                o1.x = fmaf(a, m0, fmaf(bw, m1, fmaf(c, m2, o1.x)));
                o1.y = fmaf(a, m1, fmaf(bw, m2, fmaf(c, m3, o1.y)));
                o1.z = fmaf(a, m2, fmaf(bw, m3, fmaf(c, m4, o1.z)));
                o1.w = fmaf(a, m3, fmaf(bw, m4, fmaf(c, m5, o1.w)));
            }
            {
                const float* tr = &t2[row + dy][4 + x4];
                float m0 = tr[-1], m1 = tr[0], m2 = tr[1], m3 = tr[2], m4 = tr[3], m5 = tr[4];
                float a = wB[dy * 3 + 0], bw = wB[dy * 3 + 1], c = wB[dy * 3 + 2];
                o2.x = fmaf(a, m0, fmaf(bw, m1, fmaf(c, m2, o2.x)));
                o2.y = fmaf(a, m1, fmaf(bw, m2, fmaf(c, m3, o2.y)));
                o2.z = fmaf(a, m2, fmaf(bw, m3, fmaf(c, m4, o2.z)));
                o2.w = fmaf(a, m3, fmaf(bw, m4, fmaf(c, m5, o2.w)));
            }
        }
        float4 g;
        g.x = gelu_exact(o1.x) * o2.x;
        g.y = gelu_exact(o1.y) * o2.y;
        g.z = gelu_exact(o1.z) * o2.z;
        g.w = gelu_exact(o1.w) * o2.w;
        *(float4*)&out[baseo + (y0 + row) * 128 + x4] = g;
    }
}

// ---------------------------------------------------------------------------
// 3) Attention logits + fused sq-norm partials
// ---------------------------------------------------------------------------
__global__ __launch_bounds__(256) void attn_logits_k(const float* __restrict__ qkv)
{
    int seg = blockIdx.x;
    int bh  = blockIdx.y;
    int b = bh >> 3, h = bh & 7;
    const float* qb = qkv + ((size_t)b * 384 + h * DHEAD) * HW + seg * 128;
    const float* kb = qkv + ((size_t)b * 384 + 128 + h * DHEAD) * HW + seg * 128;

    __shared__ __align__(16) float qs[16][132];
    __shared__ __align__(16) float ks[16][132];

    int tid = threadIdx.x;
#pragma unroll
    for (int t = 0; t < 2; t++) {
        int idx = tid + t * 256;
        int row = idx >> 5, c4 = (idx & 31) << 2;
        *(float4*)&qs[row][c4] = *(const float4*)&qb[(size_t)row * HW + c4];
        *(float4*)&ks[row][c4] = *(const float4*)&kb[(size_t)row * HW + c4];
    }
    __syncthreads();

    int i = tid >> 4, j = tid & 15;
    bool diag = (i == j);
    const float4* q4 = (const float4*)&qs[i][0];
    const float4* k4 = (const float4*)&ks[j][0];
    float acc = 0.f, q2 = 0.f, k2 = 0.f;
#pragma unroll 8
    for (int n4 = 0; n4 < 32; n4++) {
        float4 a = q4[n4];
        float4 c = k4[n4];
        acc = fmaf(a.x, c.x, acc); acc = fmaf(a.y, c.y, acc);
        acc = fmaf(a.z, c.z, acc); acc = fmaf(a.w, c.w, acc);
        if (diag) {
            q2 = fmaf(a.x, a.x, q2); q2 = fmaf(a.y, a.y, q2);
            q2 = fmaf(a.z, a.z, q2); q2 = fmaf(a.w, a.w, q2);
            k2 = fmaf(c.x, c.x, k2); k2 = fmaf(c.y, c.y, k2);
            k2 = fmaf(c.z, c.z, k2); k2 = fmaf(c.w, c.w, k2);
        }
    }

    int slot = bh * ALOG_SEGS + seg;
    g_partS[(size_t)slot * 256 + tid] = acc;
    if (diag) {
        g_partQ2[slot * 16 + i] = q2;
        g_partK2[slot * 16 + i] = k2;
    }
}

// ---------------------------------------------------------------------------
// 4) Finalize: reduce segments, l2norm scale, temperature, softmax
// ---------------------------------------------------------------------------
__global__ __launch_bounds__(256) void attn_finalize_k(const float* __restrict__ temp)
{
    int bh = blockIdx.x;
    int h = bh & 7;
    int i = threadIdx.x >> 4, j = threadIdx.x & 15;

    float s = 0.f, q2 = 0.f, k2 = 0.f;
    for (int seg = 0; seg < ALOG_SEGS; seg++) {
        int slot = bh * ALOG_SEGS + seg;
        s  += g_partS [(size_t)slot * 256 + threadIdx.x];
        q2 += g_partQ2[slot * 16 + i];
        k2 += g_partK2[slot * 16 + j];
    }
    float rq = 1.f / fmaxf(sqrtf(q2), 1e-12f);
    float rk = 1.f / fmaxf(sqrtf(k2), 1e-12f);
    s = s * rq * rk * temp[h];

    float m = s;
    m = fmaxf(m, __shfl_xor_sync(0xffffffffu, m, 8, 16));
    m = fmaxf(m, __shfl_xor_sync(0xffffffffu, m, 4, 16));
    m = fmaxf(m, __shfl_xor_sync(0xffffffffu, m, 2, 16));
    m = fmaxf(m, __shfl_xor_sync(0xffffffffu, m, 1, 16));
    float e = expf(s - m);
    float sum = e;
    sum += __shfl_xor_sync(0xffffffffu, sum, 8, 16);
    sum += __shfl_xor_sync(0xffffffffu, sum, 4, 16);
    sum += __shfl_xor_sync(0xffffffffu, sum, 2, 16);
    sum += __shfl_xor_sync(0xffffffffu, sum, 1, 16);
    g_attn[bh * 256 + threadIdx.x] = e / sum;
}

// ---------------------------------------------------------------------------
// 5) Effective proj weights: plain fp32 + 128-row hi/lo image
// ---------------------------------------------------------------------------
__global__ __launch_bounds__(256) void weff_k(const float* __restrict__ proj_w)
{
    int b = blockIdx.x, h = blockIdx.y;
    __shared__ float at[16][16];
    __shared__ float pw[128][16];
    int tid = threadIdx.x;

    at[tid >> 4][tid & 15] = g_attn[(b * 8 + h) * 256 + tid];
#pragma unroll
    for (int t = 0; t < 8; t++) {
        int idx = tid + t * 256;
        int o = idx >> 4, i = idx & 15;
        pw[o][i] = proj_w[o * 128 + h * 16 + i];
    }
    __syncthreads();

    uint8_t* img = g_WeffT + (size_t)b * 65536;
#pragma unroll
    for (int t = 0; t < 8; t++) {
        int idx = tid + t * 256;
        int o = idx >> 4, e = idx & 15;
        float s = 0.f;
#pragma unroll
        for (int i = 0; i < 16; i++) s = fmaf(pw[o][i], at[i][e], s);
        g_Weff[((size_t)b * 128 + o) * 128 + h * 16 + e] = s;
        __nv_bfloat16 hb = __float2bfloat16(s);
        __nv_bfloat16 lb = __float2bfloat16(s - __bfloat162float(hb));
        int kk = h * 16 + e;
        *(__nv_bfloat16*)(img + img128(o, kk))       = hb;
        *(__nv_bfloat16*)(img + img128(o, 128 + kk)) = lb;
    }
}

// ---------------------------------------------------------------------------
// Launch
// ---------------------------------------------------------------------------
extern "C" void kernel_launch(void* const* d_in, const int* in_sizes, int n_in,
                              void* d_out, int out_size)
{
    const float* x      = (const float*)d_in[0];
    const float* ln1_w  = (const float*)d_in[1];
    const float* ln1_b  = (const float*)d_in[2];
    const float* temp   = (const float*)d_in[3];
    const float* qkv_pw = (const float*)d_in[4];
    const float* qkv_dw = (const float*)d_in[5];
    const float* proj_w = (const float*)d_in[6];
    const float* ln2_w  = (const float*)d_in[7];
    const float* ln2_b  = (const float*)d_in[8];
    const float* g1_w   = (const float*)d_in[9];
    const float* gd_w   = (const float*)d_in[10];
    const float* g2_w   = (const float*)d_in[11];
    float* out = (float*)d_out;

    float *bufA, *bufB, *WqP, *Wg1P, *Wg2P, *rs, *cb, *Weff, *mu, *rstd;
    uint8_t *WqT, *Wg1T, *Wg2T, *WeffT;
    cudaGetSymbolAddress((void**)&bufA,  g_bufA);
    cudaGetSymbolAddress((void**)&bufB,  g_bufB);
    cudaGetSymbolAddress((void**)&WqP,   g_WqP);
    cudaGetSymbolAddress((void**)&Wg1P,  g_Wg1P);
    cudaGetSymbolAddress((void**)&Wg2P,  g_Wg2P);
    cudaGetSymbolAddress((void**)&rs,    g_rs);
    cudaGetSymbolAddress((void**)&cb,    g_cb);
    cudaGetSymbolAddress((void**)&Weff,  g_Weff);
    cudaGetSymbolAddress((void**)&mu,    g_mu);
    cudaGetSymbolAddress((void**)&rstd,  g_rstd);
    cudaGetSymbolAddress((void**)&WqT,   g_WqT);
    cudaGetSymbolAddress((void**)&Wg1T,  g_Wg1T);
    cudaGetSymbolAddress((void**)&Wg2T,  g_Wg2T);
    cudaGetSymbolAddress((void**)&WeffT, g_WeffT);

    const int sm128 = 1024 + 65536 + 65536 + 8448;    // 140,544
    const int sm256 = 1024 + 65536 + 131072 + 8448;   // 206,080
    cudaFuncSetAttribute(gemm5<1, false, 128, 3>, cudaFuncAttributeMaxDynamicSharedMemorySize, sm128);
    cudaFuncSetAttribute(gemm5<3, true, 128, 1>,  cudaFuncAttributeMaxDynamicSharedMemorySize, sm128);
    cudaFuncSetAttribute(gemm5<1, false, 128, 4>, cudaFuncAttributeMaxDynamicSharedMemorySize, sm128);
    cudaFuncSetAttribute(gemm5<0, true, 256, 1>,  cudaFuncAttributeMaxDynamicSharedMemorySize, sm256);

    dim3 b256(256);
    dim3 ggrid(HW / 128, BATCH);

    prep_w_k<<<128, b256>>>(qkv_pw, ln1_w, ln1_b, g1_w, ln2_w, ln2_b, g2_w);

    // --- MDTA ---
    ln_stats_k<<<dim3(16, BATCH), b256>>>(x, mu, rstd);
    gemm5<1, false, 128, 3><<<ggrid, b256, sm128>>>(
        WqT, 0, WqP, 0, x, mu, rstd, rs, cb, nullptr, bufA, 384, 128);
    dwconv_k<<<dim3(4, BATCH * 384), b256>>>(bufA, qkv_dw, bufB, 384);
    attn_logits_k<<<dim3(ALOG_SEGS, 32), b256>>>(bufB);
    attn_finalize_k<<<32, b256>>>(temp);
    weff_k<<<dim3(4, 8), b256>>>(proj_w);
    // x2 = x + Weff_b * v ; emits LN stats of x2
    gemm5<3, true, 128, 1><<<ggrid, b256, sm128>>>(
        WeffT, 65536, Weff, 16384,
        bufB + (size_t)256 * HW, mu, rstd, nullptr, nullptr,
        x, out, 128, 384);

    // --- GDFN ---
    gemm5<1, false, 128, 4><<<ggrid, b256, sm128>>>(
        Wg1T, 0, Wg1P, 0, out, mu, rstd, rs + 384, cb + 384, nullptr, bufA, 512, 128);
    dwgate_k<<<dim3(4, BATCH * 256), b256>>>(bufA, gd_w, bufB);
    gemm5<0, true, 256, 1><<<ggrid, b256, sm256>>>(
        Wg2T, 0, Wg2P, 0, bufB, nullptr, nullptr, nullptr, nullptr,
        out, out, 128, 256);
}